// round 15
// baseline (speedup 1.0000x reference)
#include <cuda_runtime.h>
#include <math.h>
#include <stdint.h>

// Problem constants (fixed shapes per reference)
#define DEPTH    8
#define NN       255        // internal nodes
#define NL       256        // leaves (K dim)
#define NCLS     200        // classes
#define BT       16         // batch tile per block
#define KS       5          // k-split factor (chunks 52,51,51,51,51)

// ---- smem layout (bytes) ----
// [0..16)          : mbarrier (+pad)
// [16..20496)      : s_ew [256 leaves][stride 20 floats] = 20,480 B
//                    phases A/B first use this region for the er table
//                    [255 nodes][stride 20] = 20,400 B, then overwrite with EW
// [20496..225296)  : s_el [256 k][200 floats] = 204,800 B (single TMA)
// [..+1024)        : pad for harmless prefetch over-reads
#define MBAR_BYTES   16
#define EW_FLOATS    (NL * 20)                  // 5120
#define EL_FLOATS    (NL * NCLS)                // 51200
#define PAD_BYTES    1024
#define SMEM_BYTES   (MBAR_BYTES + (EW_FLOATS + EL_FLOATS) * 4 + PAD_BYTES)

// exp(-1e-7): P_left = 1 - exp(-(|s|+eps)) = 1 - exp(s)*exp(-eps) for s <= 0
#define EXP_NEG_EPS  0.99999990f

__device__ __align__(16) float g_EL[NL * NCLS];

typedef unsigned long long u64;

__device__ __forceinline__ u64 pk2(float lo, float hi) {
    u64 r;
    asm("mov.b64 %0, {%1, %2};" : "=l"(r) : "f"(lo), "f"(hi));
    return r;
}
__device__ __forceinline__ u64 fma2(u64 a, u64 b, u64 c) {
    u64 d;
    asm("fma.rn.f32x2 %0, %1, %2, %3;" : "=l"(d) : "l"(a), "l"(b), "l"(c));
    return d;
}
__device__ __forceinline__ void upk2(u64 v, float& lo, float& hi) {
    asm("mov.b64 {%0, %1}, %2;" : "=f"(lo), "=f"(hi) : "l"(v));
}

// fma-pipe exp for s <= 0 (range here: [-3.02, 0]); rel err ~1.4e-7.
// Magic-number round-to-nearest; scale rebuilt from the magic's low bits.
__device__ __forceinline__ float fast_exp(float s) {
    const float t     = s * 1.44269504f;           // log2(e)
    const float magic = t + 12582912.0f;           // 1.5 * 2^23
    const float r     = magic - 12582912.0f;
    const float f     = t - r;                     // f in [-0.5, 0.5]
    float q = fmaf(f, 1.54035304e-4f, 1.33335581e-3f);
    q = fmaf(f, q, 9.61812910e-3f);
    q = fmaf(f, q, 5.55041087e-2f);
    q = fmaf(f, q, 2.40226507e-1f);
    q = fmaf(f, q, 6.93147182e-1f);
    const float p = fmaf(f, q, 1.0f);              // 2^f
    const int   sc = (__float_as_int(magic) + 127) << 23;   // 2^n
    return p * __int_as_float(sc);
}

// fma-pipe natural log for normal positive a; abs err ~1.5e-5.
// Mantissa reduced to [sqrt(2)/2, sqrt(2)), degree-9 ln(1+u) Taylor-Horner.
__device__ __forceinline__ float fast_log(float a) {
    const int   i = __float_as_int(a);
    const int   e = (i - 0x3F3504F3) >> 23;                // arithmetic shift
    const float m = __int_as_float(i - (e << 23));         // [0.7071, 1.4142)
    const float u = m - 1.0f;                              // [-0.2929, 0.4142)
    float p = fmaf(u, 0.111111111f, -0.125f);
    p = fmaf(u, p, 0.142857143f);
    p = fmaf(u, p, -0.166666667f);
    p = fmaf(u, p, 0.2f);
    p = fmaf(u, p, -0.25f);
    p = fmaf(u, p, 0.333333333f);
    p = fmaf(u, p, -0.5f);
    p = fmaf(u, p, 1.0f);
    return fmaf((float)e, 0.693147181f, u * p);
}

__device__ __forceinline__ uint32_t smem_u32(const void* p) {
    uint32_t a;
    asm("{ .reg .u64 t; cvta.to.shared.u64 t, %1; cvt.u32.u64 %0, t; }"
        : "=r"(a) : "l"(p));
    return a;
}
__device__ __forceinline__ void mbar_init(uint32_t mbar, uint32_t cnt) {
    asm volatile("mbarrier.init.shared.b64 [%0], %1;" :: "r"(mbar), "r"(cnt) : "memory");
}
__device__ __forceinline__ void mbar_expect_tx(uint32_t mbar, uint32_t bytes) {
    asm volatile("mbarrier.arrive.expect_tx.shared.b64 _, [%0], %1;"
                 :: "r"(mbar), "r"(bytes) : "memory");
}
__device__ __forceinline__ void bulk_copy_g2s(uint32_t dst, const void* src,
                                              uint32_t bytes, uint32_t mbar) {
    asm volatile(
        "cp.async.bulk.shared::cluster.global.mbarrier::complete_tx::bytes "
        "[%0], [%1], %2, [%3];"
        :: "r"(dst), "l"(src), "r"(bytes), "r"(mbar) : "memory");
}
__device__ __forceinline__ void mbar_wait(uint32_t mbar, uint32_t parity) {
    uint32_t done;
    asm volatile(
        "{\n\t.reg .pred p;\n\t"
        "mbarrier.try_wait.parity.acquire.cta.shared::cta.b64 p, [%1], %2;\n\t"
        "selp.b32 %0, 1, 0, p;\n\t}"
        : "=r"(done) : "r"(mbar), "r"(parity) : "memory");
    if (!done) {
        asm volatile(
            "{\n\t.reg .pred P1;\n\t"
            "W%=:\n\t"
            "mbarrier.try_wait.parity.acquire.cta.shared::cta.b64 P1, [%0], %1, 0x989680;\n\t"
            "@P1 bra.uni D%=;\n\t"
            "bra.uni W%=;\n\t"
            "D%=:\n\t}"
            :: "r"(mbar), "r"(parity) : "memory");
    }
}
// PDL: wait until the preceding (primary) grid's memory is visible
__device__ __forceinline__ void grid_dep_wait() {
    asm volatile("griddepcontrol.wait;" ::: "memory");
}

// ---------------- kernel 1: row softmax of leaf_logits ----------------
// one row per 32-thread block (256 blocks). Uses MUFU (__expf) on purpose:
// it overlaps gemm phase A (fma-pipe) on the same SMs via PDL.
__global__ void leaf_softmax_kernel(const float* __restrict__ logits) {
    const int lane = threadIdx.x;
    const int leaf = blockIdx.x;
    const float* row = logits + leaf * NCLS;

    float v[7];
    float s = 0.f;
#pragma unroll
    for (int i = 0; i < 7; i++) {
        int c = lane + 32 * i;
        v[i] = (c < NCLS) ? __expf(row[c]) : 0.0f;
        s += v[i];
    }
#pragma unroll
    for (int o = 16; o; o >>= 1) s += __shfl_xor_sync(0xffffffffu, s, o);

    const float r = 1.0f / s;
#pragma unroll
    for (int i = 0; i < 7; i++) {
        int c = lane + 32 * i;
        if (c < NCLS) g_EL[leaf * NCLS + c] = v[i] * r;
    }
}

// Software-pipelined GEMM inner loop: n iterations, prefetch depth 1.
// ew steps by 5 float4 per k, el steps by 50 ulonglong2 per k. EL is consumed
// directly as packed f32x2 halves of the LDS.128 (no packing movs). The final
// prefetch over-reads one iteration past the range (lands in pad/adjacent
// smem; values never consumed).
__device__ __forceinline__ void gemm_run(const float4* __restrict__ ew,
                                         const ulonglong2* __restrict__ el,
                                         int n, u64 (&acc)[4][2]) {
    float4 w = ew[0];
    ulonglong2 e = el[0];
#pragma unroll 4
    for (int i = 0; i < n; i++) {
        const float4 wn     = ew[(i + 1) * 5];    // prefetch next iteration
        const ulonglong2 en = el[(i + 1) * 50];
        u64 wd;
        wd = pk2(w.x, w.x);
        acc[0][0] = fma2(wd, e.x, acc[0][0]);
        acc[0][1] = fma2(wd, e.y, acc[0][1]);
        wd = pk2(w.y, w.y);
        acc[1][0] = fma2(wd, e.x, acc[1][0]);
        acc[1][1] = fma2(wd, e.y, acc[1][1]);
        wd = pk2(w.z, w.z);
        acc[2][0] = fma2(wd, e.x, acc[2][0]);
        acc[2][1] = fma2(wd, e.y, acc[2][1]);
        wd = pk2(w.w, w.w);
        acc[3][0] = fma2(wd, e.x, acc[3][0]);
        acc[3][1] = fma2(wd, e.y, acc[3][1]);
        w = wn;
        e = en;
    }
}

// ---------------- kernel 2: fused tree-walk + GEMM + log ----------------
// grid = 128 (B/16), 1024 threads. PDL-overlapped with the softmax grid:
// threads 1..1023 run phases A/B immediately; tid 0 waits for the softmax
// grid, then issues the single full-EL TMA. All exp/log on the fma pipe.
__global__ __launch_bounds__(1024, 1)
void tree_gemm_kernel(const float* __restrict__ sims, float* __restrict__ out,
                      const int B) {
    extern __shared__ __align__(16) char smraw[];
    const uint32_t mbarA = smem_u32(smraw);        // full EL copy
    float* s_ew = (float*)(smraw + MBAR_BYTES);    // [leaf][20] (er table first)
    float* s_el = s_ew + EW_FLOATS;                // [k][200]
    float* s_er = s_ew;                            // [node][20] (phases A/B)

    const int tid = threadIdx.x;
    const int b0  = blockIdx.x * BT;

    if (tid == 0) {
        // PDL join: block until softmax's g_EL writes are grid-visible,
        // then stream the whole EL matrix via one bulk TMA.
        mbar_init(mbarA, 1);
        asm volatile("fence.proxy.async.shared::cta;" ::: "memory");
        grid_dep_wait();
        mbar_expect_tx(mbarA, EL_FLOATS * 4);
        bulk_copy_g2s(smem_u32(s_el), g_EL, EL_FLOATS * 4, mbarA);
    } else if (tid <= NN * 4) {
        // ---- Phase A: er[node][b] = exp(sims[node, b0+b]) (1020 jobs) ----
        const int i = tid - 1;
        const int n = i >> 2;
        const int q = i & 3;
        const float4 s = *(const float4*)(sims + (size_t)n * B + b0 + q * 4);
        float4 e;
        e.x = fast_exp(s.x);
        e.y = fast_exp(s.y);
        e.z = fast_exp(s.z);
        e.w = fast_exp(s.w);
        *(float4*)(s_er + n * 20 + q * 4) = e;
    }
    __syncthreads();

    // ---- Phase B: per-leaf path products (held in registers) ----
    // P(right) = er;  P(left) = 1 - er * exp(-eps)   (sims are log-probs <= 0)
    float4 w;
    {
        const int leaf = tid >> 2;          // 0..255
        const int bq   = tid & 3;           // batch quad 0..3
        w = make_float4(1.f, 1.f, 1.f, 1.f);
        int node = 0;
#pragma unroll
        for (int lvl = 0; lvl < DEPTH; lvl++) {
            const int bit = (leaf >> (7 - lvl)) & 1;
            const float4 e = *(const float4*)(s_er + node * 20 + bq * 4);
            float4 f;
            f.x = bit ? e.x : fmaf(-e.x, EXP_NEG_EPS, 1.0f);
            f.y = bit ? e.y : fmaf(-e.y, EXP_NEG_EPS, 1.0f);
            f.z = bit ? e.z : fmaf(-e.z, EXP_NEG_EPS, 1.0f);
            f.w = bit ? e.w : fmaf(-e.w, EXP_NEG_EPS, 1.0f);
            w.x *= f.x; w.y *= f.y; w.z *= f.z; w.w *= f.w;
            node = 2 * node + 1 + bit;
        }
    }
    __syncthreads();   // all er reads done
    // overwrite er table with EW[leaf][b]
    *(float4*)(s_ew + (tid >> 2) * 20 + (tid & 3) * 4) = w;
    __syncthreads();

    mbar_wait(mbarA, 0);   // full EL resident (copy overlapped phase B)

    // ---- Phase C: k-split GEMM (KS=5, chunks 52,51,51,51,51) ----
    const int ks = tid / 200;            // 0..4 active, 5 = idle (tid>=1000)
    const int r  = tid - ks * 200;       // 0..199
    const int bg = r & 3;                // batch quad
    const int cg = r >> 2;               // class quad 0..49
    const bool active = (tid < 1000);

    u64 acc[4][2];
#pragma unroll
    for (int i = 0; i < 4; i++) { acc[i][0] = 0ull; acc[i][1] = 0ull; }

    if (active) {
        const int kbase = ks * 51 + (ks > 0 ? 1 : 0);   // 0,52,103,154,205
        const float4*     ew = (const float4*)s_ew + kbase * 5 + bg;
        const ulonglong2* el = (const ulonglong2*)s_el + kbase * 50 + cg;
        gemm_run(ew, el, (ks == 0) ? 52 : 51, acc);
    }

    // ---- all groups write partials in output-float4 order ----
    __syncthreads();   // all reads of s_ew/s_el done
    float4* part4 = (float4*)s_el;   // 5*800 float4 = 64,000 B << 204,800 B
    if (active) {
#pragma unroll
        for (int i = 0; i < 4; i++) {
            float x0, x1, x2, x3;
            upk2(acc[i][0], x0, x1);
            upk2(acc[i][1], x2, x3);
            const int q = (bg * 4 + i) * 50 + cg;
            part4[ks * 800 + q] = make_float4(x0, x1, x2, x3);
        }
    }
    __syncthreads();

    // ---- Epilogue: 800 threads, 5-way sum + fast_log + coalesced store ----
    if (tid < 800) {
        float4 a = part4[tid];
#pragma unroll
        for (int s = 1; s < KS; s++) {
            const float4 p = part4[s * 800 + tid];
            a.x += p.x; a.y += p.y; a.z += p.z; a.w += p.w;
        }
        const int b  = b0 + tid / 50;
        const int c0 = (tid % 50) * 4;
        if (b < B) {
            float4 o;
            o.x = fast_log(a.x);
            o.y = fast_log(a.y);
            o.z = fast_log(a.z);
            o.w = fast_log(a.w);
            *((float4*)(out + (size_t)b * NCLS + c0)) = o;
        }
    }
}

extern "C" void kernel_launch(void* const* d_in, const int* in_sizes, int n_in,
                              void* d_out, int out_size) {
    const float* sims   = (const float*)d_in[0];
    const float* logits = (const float*)d_in[1];
    int sims_sz = in_sizes[0];
    if (n_in >= 2 && in_sizes[0] == NL * NCLS) {   // defensive input-order check
        const float* tmp = sims; sims = logits; logits = tmp;
        sims_sz = in_sizes[1];
    }
    const int B = sims_sz / NN;   // 2048

    cudaFuncSetAttribute(tree_gemm_kernel,
                         cudaFuncAttributeMaxDynamicSharedMemorySize, SMEM_BYTES);

    // primary: softmax grid (256 single-warp blocks)
    leaf_softmax_kernel<<<NL, 32>>>(logits);

    // secondary: gemm grid, launched with programmatic stream serialization
    // so it overlaps the softmax grid; tid 0 joins via griddepcontrol.wait.
    cudaLaunchConfig_t cfg = {};
    cfg.gridDim  = dim3((B + BT - 1) / BT, 1, 1);
    cfg.blockDim = dim3(1024, 1, 1);
    cfg.dynamicSmemBytes = SMEM_BYTES;
    cfg.stream = 0;
    cudaLaunchAttribute attrs[1];
    attrs[0].id = cudaLaunchAttributeProgrammaticStreamSerialization;
    attrs[0].val.programmaticStreamSerializationAllowed = 1;
    cfg.attrs = attrs;
    cfg.numAttrs = 1;
    cudaLaunchKernelEx(&cfg, tree_gemm_kernel, sims, (float*)d_out, B);
}

// round 16
// speedup vs baseline: 1.0019x; 1.0019x over previous
#include <cuda_runtime.h>
#include <math.h>
#include <stdint.h>

// Problem constants (fixed shapes per reference)
#define DEPTH    8
#define NN       255        // internal nodes
#define NL       256        // leaves (K dim)
#define NCLS     200        // classes
#define BT       16         // batch tile per block
#define KS       10         // k-split factor (6 chunks of 26, 4 of 25)

// ---- smem layout (bytes) ----
// [0..16)          : mbarrier (+pad)
// [16..20496)      : s_ew [256 leaves][stride 20 floats] = 20,480 B
//                    phases A/B first use this region for the er table
//                    [255 nodes][stride 20] = 20,400 B, then overwrite with EW
// [20496..225296)  : s_el [256 k][200 floats] = 204,800 B (single TMA)
// [..+1024)        : pad for harmless prefetch over-reads
#define MBAR_BYTES   16
#define EW_FLOATS    (NL * 20)                  // 5120
#define EL_FLOATS    (NL * NCLS)                // 51200
#define PAD_BYTES    1024
#define SMEM_BYTES   (MBAR_BYTES + (EW_FLOATS + EL_FLOATS) * 4 + PAD_BYTES)

// exp(-1e-7): P_left = 1 - exp(-(|s|+eps)) = 1 - exp(s)*exp(-eps) for s <= 0
#define EXP_NEG_EPS  0.99999990f

__device__ __align__(16) float g_EL[NL * NCLS];

typedef unsigned long long u64;

__device__ __forceinline__ u64 pk2(float lo, float hi) {
    u64 r;
    asm("mov.b64 %0, {%1, %2};" : "=l"(r) : "f"(lo), "f"(hi));
    return r;
}
__device__ __forceinline__ u64 fma2(u64 a, u64 b, u64 c) {
    u64 d;
    asm("fma.rn.f32x2 %0, %1, %2, %3;" : "=l"(d) : "l"(a), "l"(b), "l"(c));
    return d;
}
__device__ __forceinline__ void upk2(u64 v, float& lo, float& hi) {
    asm("mov.b64 {%0, %1}, %2;" : "=f"(lo), "=f"(hi) : "l"(v));
}

__device__ __forceinline__ uint32_t smem_u32(const void* p) {
    uint32_t a;
    asm("{ .reg .u64 t; cvta.to.shared.u64 t, %1; cvt.u32.u64 %0, t; }"
        : "=r"(a) : "l"(p));
    return a;
}
__device__ __forceinline__ void mbar_init(uint32_t mbar, uint32_t cnt) {
    asm volatile("mbarrier.init.shared.b64 [%0], %1;" :: "r"(mbar), "r"(cnt) : "memory");
}
__device__ __forceinline__ void mbar_expect_tx(uint32_t mbar, uint32_t bytes) {
    asm volatile("mbarrier.arrive.expect_tx.shared.b64 _, [%0], %1;"
                 :: "r"(mbar), "r"(bytes) : "memory");
}
__device__ __forceinline__ void bulk_copy_g2s(uint32_t dst, const void* src,
                                              uint32_t bytes, uint32_t mbar) {
    asm volatile(
        "cp.async.bulk.shared::cluster.global.mbarrier::complete_tx::bytes "
        "[%0], [%1], %2, [%3];"
        :: "r"(dst), "l"(src), "r"(bytes), "r"(mbar) : "memory");
}
__device__ __forceinline__ void mbar_wait(uint32_t mbar, uint32_t parity) {
    uint32_t done;
    asm volatile(
        "{\n\t.reg .pred p;\n\t"
        "mbarrier.try_wait.parity.acquire.cta.shared::cta.b64 p, [%1], %2;\n\t"
        "selp.b32 %0, 1, 0, p;\n\t}"
        : "=r"(done) : "r"(mbar), "r"(parity) : "memory");
    if (!done) {
        asm volatile(
            "{\n\t.reg .pred P1;\n\t"
            "W%=:\n\t"
            "mbarrier.try_wait.parity.acquire.cta.shared::cta.b64 P1, [%0], %1, 0x989680;\n\t"
            "@P1 bra.uni D%=;\n\t"
            "bra.uni W%=;\n\t"
            "D%=:\n\t}"
            :: "r"(mbar), "r"(parity) : "memory");
    }
}
// PDL: wait until the preceding (primary) grid's memory is visible
__device__ __forceinline__ void grid_dep_wait() {
    asm volatile("griddepcontrol.wait;" ::: "memory");
}

// ---------------- kernel 1: row softmax of leaf_logits ----------------
// one row per 32-thread block (256 blocks). MUFU __expf on purpose — it
// overlaps gemm phase A (fma-pipe) on the same SMs via PDL.
__global__ void leaf_softmax_kernel(const float* __restrict__ logits) {
    const int lane = threadIdx.x;
    const int leaf = blockIdx.x;
    const float* row = logits + leaf * NCLS;

    float v[7];
    float s = 0.f;
#pragma unroll
    for (int i = 0; i < 7; i++) {
        int c = lane + 32 * i;
        v[i] = (c < NCLS) ? __expf(row[c]) : 0.0f;
        s += v[i];
    }
#pragma unroll
    for (int o = 16; o; o >>= 1) s += __shfl_xor_sync(0xffffffffu, s, o);

    const float r = 1.0f / s;
#pragma unroll
    for (int i = 0; i < 7; i++) {
        int c = lane + 32 * i;
        if (c < NCLS) g_EL[leaf * NCLS + c] = v[i] * r;
    }
}

// Software-pipelined 4b x 8c GEMM inner loop: n iterations, prefetch depth 1.
// ew steps by 5 float4 per k; el is two adjacent ulonglong2 (8 classes),
// stepping by 50 ulonglong2 per k. EL consumed directly as packed f32x2
// halves of the LDS.128 (no packing movs). Final prefetch over-reads one
// iteration (lands in pad/adjacent smem; values never consumed).
__device__ __forceinline__ void gemm_run(const float4* __restrict__ ew,
                                         const ulonglong2* __restrict__ el,
                                         int n, u64 (&acc)[4][4]) {
    float4 w      = ew[0];
    ulonglong2 e0 = el[0];
    ulonglong2 e1 = el[1];
#pragma unroll 2
    for (int i = 0; i < n; i++) {
        const float4 wn      = ew[(i + 1) * 5];    // prefetch next iteration
        const ulonglong2 en0 = el[(i + 1) * 50];
        const ulonglong2 en1 = el[(i + 1) * 50 + 1];
        u64 wd;
        wd = pk2(w.x, w.x);
        acc[0][0] = fma2(wd, e0.x, acc[0][0]);
        acc[0][1] = fma2(wd, e0.y, acc[0][1]);
        acc[0][2] = fma2(wd, e1.x, acc[0][2]);
        acc[0][3] = fma2(wd, e1.y, acc[0][3]);
        wd = pk2(w.y, w.y);
        acc[1][0] = fma2(wd, e0.x, acc[1][0]);
        acc[1][1] = fma2(wd, e0.y, acc[1][1]);
        acc[1][2] = fma2(wd, e1.x, acc[1][2]);
        acc[1][3] = fma2(wd, e1.y, acc[1][3]);
        wd = pk2(w.z, w.z);
        acc[2][0] = fma2(wd, e0.x, acc[2][0]);
        acc[2][1] = fma2(wd, e0.y, acc[2][1]);
        acc[2][2] = fma2(wd, e1.x, acc[2][2]);
        acc[2][3] = fma2(wd, e1.y, acc[2][3]);
        wd = pk2(w.w, w.w);
        acc[3][0] = fma2(wd, e0.x, acc[3][0]);
        acc[3][1] = fma2(wd, e0.y, acc[3][1]);
        acc[3][2] = fma2(wd, e1.x, acc[3][2]);
        acc[3][3] = fma2(wd, e1.y, acc[3][3]);
        w = wn;
        e0 = en0;
        e1 = en1;
    }
}

// ---------------- kernel 2: fused tree-walk + GEMM + log ----------------
// grid = 128 (B/16), 1024 threads. PDL-overlapped with the softmax grid.
// 4b x 8c register tile, KS=10 k-split (1000 active mainloop threads).
__global__ __launch_bounds__(1024, 1)
void tree_gemm_kernel(const float* __restrict__ sims, float* __restrict__ out,
                      const int B) {
    extern __shared__ __align__(16) char smraw[];
    const uint32_t mbarA = smem_u32(smraw);        // full EL copy
    float* s_ew = (float*)(smraw + MBAR_BYTES);    // [leaf][20] (er table first)
    float* s_el = s_ew + EW_FLOATS;                // [k][200]
    float* s_er = s_ew;                            // [node][20] (phases A/B)

    const int tid = threadIdx.x;
    const int b0  = blockIdx.x * BT;

    if (tid == 0) {
        // PDL join: block until softmax's g_EL writes are grid-visible,
        // then stream the whole EL matrix via one bulk TMA.
        mbar_init(mbarA, 1);
        asm volatile("fence.proxy.async.shared::cta;" ::: "memory");
        grid_dep_wait();
        mbar_expect_tx(mbarA, EL_FLOATS * 4);
        bulk_copy_g2s(smem_u32(s_el), g_EL, EL_FLOATS * 4, mbarA);
    } else if (tid <= NN * 4) {
        // ---- Phase A: er[node][b] = exp(sims[node, b0+b]) (1020 jobs) ----
        const int i = tid - 1;
        const int n = i >> 2;
        const int q = i & 3;
        const float4 s = *(const float4*)(sims + (size_t)n * B + b0 + q * 4);
        float4 e;
        e.x = __expf(s.x);
        e.y = __expf(s.y);
        e.z = __expf(s.z);
        e.w = __expf(s.w);
        *(float4*)(s_er + n * 20 + q * 4) = e;
    }
    __syncthreads();

    // ---- Phase B: per-leaf path products (held in registers) ----
    // P(right) = er;  P(left) = 1 - er * exp(-eps)   (sims are log-probs <= 0)
    float4 w;
    {
        const int leaf = tid >> 2;          // 0..255
        const int bq   = tid & 3;           // batch quad 0..3
        w = make_float4(1.f, 1.f, 1.f, 1.f);
        int node = 0;
#pragma unroll
        for (int lvl = 0; lvl < DEPTH; lvl++) {
            const int bit = (leaf >> (7 - lvl)) & 1;
            const float4 e = *(const float4*)(s_er + node * 20 + bq * 4);
            float4 f;
            f.x = bit ? e.x : fmaf(-e.x, EXP_NEG_EPS, 1.0f);
            f.y = bit ? e.y : fmaf(-e.y, EXP_NEG_EPS, 1.0f);
            f.z = bit ? e.z : fmaf(-e.z, EXP_NEG_EPS, 1.0f);
            f.w = bit ? e.w : fmaf(-e.w, EXP_NEG_EPS, 1.0f);
            w.x *= f.x; w.y *= f.y; w.z *= f.z; w.w *= f.w;
            node = 2 * node + 1 + bit;
        }
    }
    __syncthreads();   // all er reads done
    // overwrite er table with EW[leaf][b]
    *(float4*)(s_ew + (tid >> 2) * 20 + (tid & 3) * 4) = w;
    __syncthreads();

    mbar_wait(mbarA, 0);   // full EL resident (copy overlapped phase B)

    // ---- Phase C: k-split GEMM (KS=10; 6 chunks of 26 k, 4 of 25 k) ----
    const int ks  = tid / 100;           // 0..9 active, >=10 idle (tid>=1000)
    const int r   = tid - ks * 100;      // 0..99
    const int bg  = r & 3;               // batch quad
    const int cg8 = r >> 2;              // class octet 0..24
    const bool active = (tid < 1000);

    u64 acc[4][4];
#pragma unroll
    for (int i = 0; i < 4; i++)
#pragma unroll
        for (int j = 0; j < 4; j++) acc[i][j] = 0ull;

    if (active) {
        const int kbase = (ks < 6) ? ks * 26 : 156 + (ks - 6) * 25;
        const int n     = (ks < 6) ? 26 : 25;
        const float4*     ew = (const float4*)s_ew + kbase * 5 + bg;
        const ulonglong2* el = (const ulonglong2*)s_el + kbase * 50 + cg8 * 2;
        gemm_run(ew, el, n, acc);
    }

    // ---- all groups write partials in output-float4 order ----
    __syncthreads();   // all reads of s_ew/s_el done
    float4* part4 = (float4*)s_el;   // 10*800 float4 = 128,000 B < 204,800 B
    if (active) {
#pragma unroll
        for (int i = 0; i < 4; i++) {
#pragma unroll
            for (int j = 0; j < 2; j++) {
                float x0, x1, x2, x3;
                upk2(acc[i][j * 2 + 0], x0, x1);
                upk2(acc[i][j * 2 + 1], x2, x3);
                const int q = (bg * 4 + i) * 50 + cg8 * 2 + j;
                part4[ks * 800 + q] = make_float4(x0, x1, x2, x3);
            }
        }
    }
    __syncthreads();

    // ---- Epilogue: 800 threads, 10-way sum + __logf + coalesced store ----
    if (tid < 800) {
        float4 a = part4[tid];
#pragma unroll
        for (int s = 1; s < KS; s++) {
            const float4 p = part4[s * 800 + tid];
            a.x += p.x; a.y += p.y; a.z += p.z; a.w += p.w;
        }
        const int b  = b0 + tid / 50;
        const int c0 = (tid % 50) * 4;
        if (b < B) {
            float4 o;
            o.x = __logf(a.x);
            o.y = __logf(a.y);
            o.z = __logf(a.z);
            o.w = __logf(a.w);
            *((float4*)(out + (size_t)b * NCLS + c0)) = o;
        }
    }
}

extern "C" void kernel_launch(void* const* d_in, const int* in_sizes, int n_in,
                              void* d_out, int out_size) {
    const float* sims   = (const float*)d_in[0];
    const float* logits = (const float*)d_in[1];
    int sims_sz = in_sizes[0];
    if (n_in >= 2 && in_sizes[0] == NL * NCLS) {   // defensive input-order check
        const float* tmp = sims; sims = logits; logits = tmp;
        sims_sz = in_sizes[1];
    }
    const int B = sims_sz / NN;   // 2048

    cudaFuncSetAttribute(tree_gemm_kernel,
                         cudaFuncAttributeMaxDynamicSharedMemorySize, SMEM_BYTES);

    // primary: softmax grid (256 single-warp blocks)
    leaf_softmax_kernel<<<NL, 32>>>(logits);

    // secondary: gemm grid, launched with programmatic stream serialization
    // so it overlaps the softmax grid; tid 0 joins via griddepcontrol.wait.
    cudaLaunchConfig_t cfg = {};
    cfg.gridDim  = dim3((B + BT - 1) / BT, 1, 1);
    cfg.blockDim = dim3(1024, 1, 1);
    cfg.dynamicSmemBytes = SMEM_BYTES;
    cfg.stream = 0;
    cudaLaunchAttribute attrs[1];
    attrs[0].id = cudaLaunchAttributeProgrammaticStreamSerialization;
    attrs[0].val.programmaticStreamSerializationAllowed = 1;
    cfg.attrs = attrs;
    cfg.numAttrs = 1;
    cudaLaunchKernelEx(&cfg, tree_gemm_kernel, sims, (float*)d_out, B);
}